// round 8
// baseline (speedup 1.0000x reference)
#include <cuda_runtime.h>
#include <cuda_bf16.h>
#include <math.h>

// Fused FastGuidedFilter, 62x30 tile, packed f32x2 (FADD2/FMUL2) arithmetic.
//   stage 1: (x,y) interleaved in smem
//   stage 2: box3x3 stats via packed (sx,sy) and (sxx,sxy) chains -> A,b interleaved
//   stage 3: packed directional sums, pre-shifted A (g = (sumA-n)*im + sumB), grouped argmin
//   out = clip(trunc(best), 0, 255).  hr_x unused by reference.

#define TW 62
#define TH 30
#define SXYW 136  // (x,y)-interleaved stride: 66 cols * 2 + 4 pad (16B multiple)
#define SABW 136  // (A,b)-interleaved stride: 64 cols * 2 + 8 pad (16B multiple)

typedef unsigned long long u64;
__device__ __forceinline__ u64 F2ADD(u64 a, u64 b) {
    u64 r; asm("add.rn.f32x2 %0, %1, %2;" : "=l"(r) : "l"(a), "l"(b)); return r;
}
__device__ __forceinline__ u64 F2MUL(u64 a, u64 b) {
    u64 r; asm("mul.rn.f32x2 %0, %1, %2;" : "=l"(r) : "l"(a), "l"(b)); return r;
}
__device__ __forceinline__ u64 F2PK(float a, float b) {
    u64 r; asm("mov.b64 %0, {%1, %2};" : "=l"(r) : "f"(a), "f"(b)); return r;
}
__device__ __forceinline__ void F2UP(u64 v, float& a, float& b) {
    asm("mov.b64 {%0, %1}, %2;" : "=f"(a), "=f"(b) : "l"(v));
}

__global__ __launch_bounds__(256, 4)
void fgf_kernel(const float* __restrict__ lrx,
                const float* __restrict__ lry,
                float* __restrict__ out,
                int H, int W)
{
    __shared__ float sxy[34 * SXYW];        // (x,y) pairs, 34 rows x 66 cols
    __shared__ float sAB[32 * SABW + 16];   // (A,b) pairs; pad for edge overreads

    const int tid = threadIdx.x;
    const int c   = blockIdx.z;
    const int gx0 = blockIdx.x * TW;
    const int gy0 = blockIdx.y * TH;
    const float* __restrict__ px = lrx + (size_t)c * H * W;
    const float* __restrict__ py = lry + (size_t)c * H * W;

    const bool xin = (gx0 >= 2) && (gx0 + TW + 2 <= W);
    const bool yin = (gy0 >= 2) && (gy0 + TH + 2 <= H);
    const bool inner = xin && yin;

    // ---- stage 1: load 34x66 halo tile, write (x,y) interleaved ----
    if (xin) {
        #pragma unroll
        for (int it = 0; it < 5; ++it) {
            int i = tid + it * 256;
            if (i < 1122) {                       // 33 col-pairs per row x 34 rows
                int r = i / 33;
                int q = (i - r * 33) * 2;         // even col
                int gy = gy0 + r - 2; gy = max(0, min(H - 1, gy));
                const float2 vx = *(const float2*)(px + (size_t)gy * W + (gx0 - 2) + q);
                const float2 vy = *(const float2*)(py + (size_t)gy * W + (gx0 - 2) + q);
                *(float4*)&sxy[r * SXYW + q * 2] = make_float4(vx.x, vy.x, vx.y, vy.y);
            }
        }
    } else {
        for (int i = tid; i < 34 * 66; i += 256) {
            int r = i / 66;
            int q = i - r * 66;
            int gy = gy0 + r - 2; gy = max(0, min(H - 1, gy));
            int gx = gx0 + q - 2; gx = max(0, min(W - 1, gx));
            size_t g = (size_t)gy * W + gx;
            sxy[r * SXYW + q * 2]     = px[g];
            sxy[r * SXYW + q * 2 + 1] = py[g];
        }
    }
    __syncthreads();

    // ---- stage 2: A,b on exact 32x64 grid, one 2x4 chunk per thread, packed stats ----
    {
        const int cr = tid >> 4;          // 0..15
        const int cq = tid & 15;          // 0..15
        const int r0 = cr * 2, q0 = cq * 4;

        u64 S0p[4], S0m[4], S1p[4], S1m[4];   // p=(sum_x,sum_y), m=(sum_xx,sum_xy)

        #pragma unroll
        for (int u = 0; u < 4; ++u) {
            const float* base = &sxy[(r0 + u) * SXYW + q0 * 2];
            ulonglong2 L0 = *(const ulonglong2*)base;
            ulonglong2 L1 = *(const ulonglong2*)(base + 4);
            ulonglong2 L2 = *(const ulonglong2*)(base + 8);
            u64 p[6] = { L0.x, L0.y, L1.x, L1.y, L2.x, L2.y };

            u64 m[6];
            #pragma unroll
            for (int v = 0; v < 6; ++v) {
                float xv_, yv_; F2UP(p[v], xv_, yv_); (void)yv_;
                m[v] = F2MUL(F2PK(xv_, xv_), p[v]);   // (x*x, x*y)
            }

            u64 hp[4], hm[4];
            #pragma unroll
            for (int d = 0; d < 4; ++d) {
                hp[d] = F2ADD(F2ADD(p[d], p[d + 1]), p[d + 2]);
                hm[d] = F2ADD(F2ADD(m[d], m[d + 1]), m[d + 2]);
            }

            if (u == 0) {
                #pragma unroll
                for (int d = 0; d < 4; ++d) { S0p[d] = hp[d]; S0m[d] = hm[d]; }
            } else if (u == 1) {
                #pragma unroll
                for (int d = 0; d < 4; ++d) {
                    S0p[d] = F2ADD(S0p[d], hp[d]); S0m[d] = F2ADD(S0m[d], hm[d]);
                    S1p[d] = hp[d];                S1m[d] = hm[d];
                }
            } else if (u == 2) {
                #pragma unroll
                for (int d = 0; d < 4; ++d) {
                    S0p[d] = F2ADD(S0p[d], hp[d]); S0m[d] = F2ADD(S0m[d], hm[d]);
                    S1p[d] = F2ADD(S1p[d], hp[d]); S1m[d] = F2ADD(S1m[d], hm[d]);
                }
            } else {
                #pragma unroll
                for (int d = 0; d < 4; ++d) {
                    S1p[d] = F2ADD(S1p[d], hp[d]); S1m[d] = F2ADD(S1m[d], hm[d]);
                }
            }
        }

        #pragma unroll
        for (int dr = 0; dr < 2; ++dr) {
            float Ao[4], Bo[4];
            #pragma unroll
            for (int dc = 0; dc < 4; ++dc) {
                float sxv, syv, sxx, sxy_;
                F2UP(dr ? S1p[dc] : S0p[dc], sxv, syv);
                F2UP(dr ? S1m[dc] : S0m[dc], sxx, sxy_);
                // A = (sxy - sx*sy/9) / (sxx - sx*sx/9 + 9*eps); b = (sy - A*sx)/9
                float t   = sxv * (-1.0f / 9.0f);
                float num = fmaf(t, syv, sxy_);
                float den = fmaf(t, sxv, sxx) + 9e-4f;
                float A = __fdividef(num, den);
                float B = (syv - A * sxv) * (1.0f / 9.0f);
                if (!inner) {
                    int gy = gy0 + r0 + dr - 1;
                    int gx = gx0 + q0 + dc - 1;
                    if (gy < 0 || gy >= H || gx < 0 || gx >= W) { A = 0.0f; B = 0.0f; }
                }
                Ao[dc] = A; Bo[dc] = B;
            }
            float* prow = &sAB[(r0 + dr) * SABW + q0 * 2];
            *(float4*)prow       = make_float4(Ao[0], Bo[0], Ao[1], Bo[1]);
            *(float4*)(prow + 4) = make_float4(Ao[2], Bo[2], Ao[3], Bo[3]);
        }
    }
    __syncthreads();

    // ---- stage 3: packed directional sums + grouped argmin, 2 rows x 4 cols per thread ----
    const int maxy = min(TH, H - gy0);
    const int maxx = min(TW, W - gx0);
    const int ty  = tid >> 4;        // 0..15
    const int tx  = tid & 15;        // 0..15
    const int oy0 = ty * 2, ox0 = tx * 4;

    if (oy0 >= maxy || ox0 >= maxx) return;   // no syncs after this point

    float* __restrict__ po = out + (size_t)c * H * W;

    const u64 C6 = F2PK(-6.0f, 0.0f);
    const u64 C4 = F2PK(-4.0f, 0.0f);
    const u64 C2 = F2PK(-2.0f, 0.0f);

    #pragma unroll
    for (int vr = 0; vr < 2; ++vr) {
        const int oy = oy0 + vr;
        if (oy >= maxy) break;

        // load 3 rows of 6 (A,b) pairs
        const float* r0p = &sAB[(oy    ) * SABW + ox0 * 2];
        const float* r1p = &sAB[(oy + 1) * SABW + ox0 * 2];
        const float* r2p = &sAB[(oy + 2) * SABW + ox0 * 2];
        ulonglong2 x00 = *(const ulonglong2*)r0p, x01 = *(const ulonglong2*)(r0p + 4), x02 = *(const ulonglong2*)(r0p + 8);
        ulonglong2 x10 = *(const ulonglong2*)r1p, x11 = *(const ulonglong2*)(r1p + 4), x12 = *(const ulonglong2*)(r1p + 8);
        ulonglong2 x20 = *(const ulonglong2*)r2p, x21 = *(const ulonglong2*)(r2p + 4), x22 = *(const ulonglong2*)(r2p + 8);
        u64 c0[6] = { x00.x, x00.y, x01.x, x01.y, x02.x, x02.y };
        u64 c1[6] = { x10.x, x10.y, x11.x, x11.y, x12.x, x12.y };
        u64 c2[6] = { x20.x, x20.y, x21.x, x21.y, x22.x, x22.y };

        // vertical combos (packed (A,b))
        u64 vpT[6], vpB[6], vt[6];
        #pragma unroll
        for (int v = 0; v < 6; ++v) {
            vpT[v] = F2ADD(c0[v], c1[v]);
            vpB[v] = F2ADD(c1[v], c2[v]);
            vt[v]  = F2ADD(vpT[v], c2[v]);
        }

        // horizontal sums, A-component pre-shifted by its normalizer
        u64 hL[5], hT[5], hB[5], hU[4], hD[4];
        #pragma unroll
        for (int q = 0; q < 5; ++q) {
            hL[q] = F2ADD(F2ADD(vt[q],  vt[q + 1]),  C6);
            hT[q] = F2ADD(F2ADD(vpT[q], vpT[q + 1]), C4);
            hB[q] = F2ADD(F2ADD(vpB[q], vpB[q + 1]), C4);
        }
        #pragma unroll
        for (int q = 0; q < 4; ++q) {
            hU[q] = F2ADD(F2ADD(hT[q], vpT[q + 2]), C2);   // (triple-6, sumB)
            hD[q] = F2ADD(F2ADD(hB[q], vpB[q + 2]), C2);
        }

        // im values (x components of interleaved pairs)
        const float* imp = &sxy[(oy0 + 2 + vr) * SXYW + (ox0 + 2) * 2];
        float4 ip0 = *(const float4*)imp;
        float4 ip1 = *(const float4*)(imp + 4);
        float imv[4] = { ip0.x, ip0.z, ip1.x, ip1.z };

        float res[4];
        #pragma unroll
        for (int vc = 0; vc < 4; ++vc) {
            float im = imv[vc];
            float a, b;
            // g = (sumA - n)*im + sumB ; candidates in reference order L,R,U,D,NW,NE,SW,SE
            F2UP(hL[vc],     a, b); float g0 = fmaf(a, im, b);
            F2UP(hL[vc + 1], a, b); float g1 = fmaf(a, im, b);
            F2UP(hU[vc],     a, b); float g2 = fmaf(a, im, b);
            F2UP(hD[vc],     a, b); float g3 = fmaf(a, im, b);
            F2UP(hT[vc],     a, b); float h0 = fmaf(a, im, b);
            F2UP(hT[vc + 1], a, b); float h1 = fmaf(a, im, b);
            F2UP(hB[vc],     a, b); float h2 = fmaf(a, im, b);
            F2UP(hB[vc + 1], a, b); float h3 = fmaf(a, im, b);

            float d6 = fabsf(g0), b6 = g0;
            if (fabsf(g1) < d6) { d6 = fabsf(g1); b6 = g1; }
            if (fabsf(g2) < d6) { d6 = fabsf(g2); b6 = g2; }
            if (fabsf(g3) < d6) { d6 = fabsf(g3); b6 = g3; }
            float d4 = fabsf(h0), b4 = h0;
            if (fabsf(h1) < d4) { d4 = fabsf(h1); b4 = h1; }
            if (fabsf(h2) < d4) { d4 = fabsf(h2); b4 = h2; }
            if (fabsf(h3) < d4) { d4 = fabsf(h3); b4 = h3; }

            // cross-group: |g4|/4 < |g6|/6  <=>  3*d4 < 2*d6 (tie -> /6 group, ref order)
            float v6 = fmaf(b6, 1.0f / 6.0f, im);
            float v4 = fmaf(b4, 0.25f, im);
            float val = (3.0f * d4 < 2.0f * d6) ? v4 : v6;
            res[vc] = fminf(fmaxf(truncf(val), 0.0f), 255.0f);
        }

        float* prow = po + (size_t)(gy0 + oy) * W + (gx0 + ox0);
        if (ox0 + 4 <= maxx) {
            // gx0+ox0 is even -> float2 stores are 8B-aligned (16B alignment not guaranteed)
            *(float2*)prow       = make_float2(res[0], res[1]);
            *(float2*)(prow + 2) = make_float2(res[2], res[3]);
        } else {
            #pragma unroll
            for (int vc = 0; vc < 4; ++vc)
                if (ox0 + vc < maxx) prow[vc] = res[vc];
        }
    }
}

extern "C" void kernel_launch(void* const* d_in, const int* in_sizes, int n_in,
                              void* d_out, int out_size)
{
    const float* lrx = (const float*)d_in[0];
    const float* lry = (const float*)d_in[1];
    // d_in[2] (hr_x) is unused by the reference computation.
    float* out = (float*)d_out;

    const int H = 2048, W = 2048;
    dim3 block(256);
    dim3 grid((W + TW - 1) / TW, (H + TH - 1) / TH, 3);
    fgf_kernel<<<grid, block>>>(lrx, lry, out, H, W);
}

// round 9
// speedup vs baseline: 1.0795x; 1.0795x over previous
#include <cuda_runtime.h>
#include <cuda_bf16.h>
#include <math.h>

// Fused FastGuidedFilter, 62x30 tile.
//   Conflict-free separate A/b smem planes (4-float thread spacing).
//   stage 2: row-streamed box3x3 stats (one 2x4 chunk/thread, exact 32x64 grid)
//   stage 3: vertical-reuse row streaming + pre-shifted grouped argmin
//            g = (sumA - n)*im + sumB ; cross-group 3|g4| < 2|g6|
//   out = clip(trunc(best), 0, 255).  hr_x unused by reference.

#define TW 62
#define TH 30
#define SXW 68   // input smem stride (34 rows x 66 cols used)
#define SAW 64   // A/b smem stride (32 rows x 64 cols, exact)

__global__ __launch_bounds__(256, 4)
void fgf_kernel(const float* __restrict__ lrx,
                const float* __restrict__ lry,
                float* __restrict__ out,
                int H, int W)
{
    __shared__ float sx[34 * SXW];
    __shared__ float sy[34 * SXW];
    __shared__ float sA[33 * SAW + 8];   // row 32 spare; +8 pad for edge col overread
    __shared__ float sB[33 * SAW + 8];

    const int tid = threadIdx.x;
    const int c   = blockIdx.z;
    const int gx0 = blockIdx.x * TW;
    const int gy0 = blockIdx.y * TH;
    const float* __restrict__ px = lrx + (size_t)c * H * W;
    const float* __restrict__ py = lry + (size_t)c * H * W;

    const bool xin = (gx0 >= 2) && (gx0 + TW + 2 <= W);
    const bool yin = (gy0 >= 2) && (gy0 + TH + 2 <= H);
    const bool inner = xin && yin;

    // ---- stage 1: load 34x66 halo tile (clamp == replicate pad) ----
    if (xin) {
        #pragma unroll
        for (int it = 0; it < 5; ++it) {
            int i = tid + it * 256;
            if (i < 1122) {                       // 33 float2 per row x 34 rows
                int r = i / 33;
                int q = (i - r * 33) * 2;
                int gy = gy0 + r - 2; gy = max(0, min(H - 1, gy));
                const float2 vx = *(const float2*)(px + (size_t)gy * W + (gx0 - 2) + q);
                const float2 vy = *(const float2*)(py + (size_t)gy * W + (gx0 - 2) + q);
                *(float2*)&sx[r * SXW + q] = vx;
                *(float2*)&sy[r * SXW + q] = vy;
            }
        }
    } else {
        for (int i = tid; i < 34 * 66; i += 256) {
            int r = i / 66;
            int q = i - r * 66;
            int gy = gy0 + r - 2; gy = max(0, min(H - 1, gy));
            int gx = gx0 + q - 2; gx = max(0, min(W - 1, gx));
            size_t g = (size_t)gy * W + gx;
            sx[r * SXW + q] = px[g];
            sy[r * SXW + q] = py[g];
        }
    }
    __syncthreads();

    // ---- stage 2: A,b on exact 32x64 grid, one 2x4 chunk per thread, row-streamed ----
    {
        const int cr = tid >> 4;          // 0..15
        const int cq = tid & 15;          // 0..15
        const int r0 = cr * 2, q0 = cq * 4;

        float S0x[4], S0y[4], S0xy[4], S0xx[4];
        float S1x[4], S1y[4], S1xy[4], S1xx[4];

        #pragma unroll
        for (int u = 0; u < 4; ++u) {
            const float* bx = &sx[(r0 + u) * SXW + q0];
            const float* by = &sy[(r0 + u) * SXW + q0];
            float4 x4 = *(const float4*)bx;
            float2 x2 = *(const float2*)(bx + 4);
            float4 y4 = *(const float4*)by;
            float2 y2 = *(const float2*)(by + 4);
            float xr[6] = { x4.x, x4.y, x4.z, x4.w, x2.x, x2.y };
            float yr[6] = { y4.x, y4.y, y4.z, y4.w, y2.x, y2.y };

            float hx[4], hy[4], hxy[4], hxx[4];
            #pragma unroll
            for (int d = 0; d < 4; ++d) {
                hx[d]  = xr[d] + xr[d+1] + xr[d+2];
                hy[d]  = yr[d] + yr[d+1] + yr[d+2];
                hxy[d] = fmaf(xr[d], yr[d], fmaf(xr[d+1], yr[d+1], xr[d+2] * yr[d+2]));
                hxx[d] = fmaf(xr[d], xr[d], fmaf(xr[d+1], xr[d+1], xr[d+2] * xr[d+2]));
            }
            if (u == 0) {
                #pragma unroll
                for (int d = 0; d < 4; ++d) { S0x[d] = hx[d]; S0y[d] = hy[d]; S0xy[d] = hxy[d]; S0xx[d] = hxx[d]; }
            } else if (u == 1) {
                #pragma unroll
                for (int d = 0; d < 4; ++d) {
                    S0x[d] += hx[d]; S0y[d] += hy[d]; S0xy[d] += hxy[d]; S0xx[d] += hxx[d];
                    S1x[d]  = hx[d]; S1y[d]  = hy[d]; S1xy[d]  = hxy[d]; S1xx[d]  = hxx[d];
                }
            } else if (u == 2) {
                #pragma unroll
                for (int d = 0; d < 4; ++d) {
                    S0x[d] += hx[d]; S0y[d] += hy[d]; S0xy[d] += hxy[d]; S0xx[d] += hxx[d];
                    S1x[d] += hx[d]; S1y[d] += hy[d]; S1xy[d] += hxy[d]; S1xx[d] += hxx[d];
                }
            } else {
                #pragma unroll
                for (int d = 0; d < 4; ++d) {
                    S1x[d] += hx[d]; S1y[d] += hy[d]; S1xy[d] += hxy[d]; S1xx[d] += hxx[d];
                }
            }
        }

        #pragma unroll
        for (int dr = 0; dr < 2; ++dr) {
            float Ao[4], Bo[4];
            #pragma unroll
            for (int dc = 0; dc < 4; ++dc) {
                float sxv = dr ? S1x[dc]  : S0x[dc];
                float syv = dr ? S1y[dc]  : S0y[dc];
                float sxy = dr ? S1xy[dc] : S0xy[dc];
                float sxx = dr ? S1xx[dc] : S0xx[dc];
                float t   = sxv * (-1.0f / 9.0f);
                float num = fmaf(t, syv, sxy);
                float den = fmaf(t, sxv, sxx) + 9e-4f;
                float A = __fdividef(num, den);
                float B = (syv - A * sxv) * (1.0f / 9.0f);
                if (!inner) {
                    int gy = gy0 + r0 + dr - 1;
                    int gx = gx0 + q0 + dc - 1;
                    if (gy < 0 || gy >= H || gx < 0 || gx >= W) { A = 0.0f; B = 0.0f; }
                }
                Ao[dc] = A; Bo[dc] = B;
            }
            *(float4*)&sA[(r0 + dr) * SAW + q0] = make_float4(Ao[0], Ao[1], Ao[2], Ao[3]);
            *(float4*)&sB[(r0 + dr) * SAW + q0] = make_float4(Bo[0], Bo[1], Bo[2], Bo[3]);
        }
    }
    __syncthreads();

    // ---- stage 3: vertical-reuse streaming + grouped argmin, 2 rows x 4 cols per thread ----
    const int maxy = min(TH, H - gy0);
    const int maxx = min(TW, W - gx0);
    const int ty  = tid >> 4;        // 0..15
    const int tx  = tid & 15;        // 0..15
    const int oy0 = ty * 2, ox0 = tx * 4;

    if (oy0 >= maxy || ox0 >= maxx) return;   // no syncs after this point

    float* __restrict__ po = out + (size_t)c * H * W;

    // helper to load one 6-col row of a plane
    #define LOADROW(arr, plane, row) { \
        const float* p_ = &plane[(row) * SAW + ox0]; \
        float4 v4_ = *(const float4*)p_; \
        float2 v2_ = *(const float2*)(p_ + 4); \
        arr[0] = v4_.x; arr[1] = v4_.y; arr[2] = v4_.z; arr[3] = v4_.w; arr[4] = v2_.x; arr[5] = v2_.y; }

    float a2[6], b2[6];               // rolling: newest loaded row
    float vpTa[6], vpBa[6], vta[6];   // vertical combos for current output row
    float vpTb[6], vpBb[6], vtb[6];
    {
        float a0[6], b0[6], a1[6], b1[6];
        LOADROW(a0, sA, oy0);     LOADROW(b0, sB, oy0);
        LOADROW(a1, sA, oy0 + 1); LOADROW(b1, sB, oy0 + 1);
        LOADROW(a2, sA, oy0 + 2); LOADROW(b2, sB, oy0 + 2);
        #pragma unroll
        for (int v = 0; v < 6; ++v) {
            vpTa[v] = a0[v] + a1[v];
            vpBa[v] = a1[v] + a2[v];
            vta[v]  = vpTa[v] + a2[v];
            vpTb[v] = b0[v] + b1[v];
            vpBb[v] = b1[v] + b2[v];
            vtb[v]  = vpTb[v] + b2[v];
        }
    }

    #pragma unroll
    for (int vr = 0; vr < 2; ++vr) {
        const int oy = oy0 + vr;
        if (oy >= maxy) break;

        if (vr == 1) {
            // advance: top-pair = old bottom-pair; load row oy0+3; new bottom-pair/triple
            float a3[6], b3[6];
            LOADROW(a3, sA, oy0 + 3); LOADROW(b3, sB, oy0 + 3);
            #pragma unroll
            for (int v = 0; v < 6; ++v) {
                vpTa[v] = vpBa[v];
                vpBa[v] = a2[v] + a3[v];
                vta[v]  = vpTa[v] + a3[v];
                vpTb[v] = vpBb[v];
                vpBb[v] = b2[v] + b3[v];
                vtb[v]  = vpTb[v] + b3[v];
            }
        }

        // horizontal sums; A-sums pre-shifted by their normalizer
        float hL6a[5], hT4a[5], hB4a[5];
        float hLb[5],  hTb[5],  hBb[5];
        float hU6a[4], hD6a[4], hUb[4], hDb[4];
        #pragma unroll
        for (int q = 0; q < 5; ++q) {
            hL6a[q] = vta[q] + vta[q+1] - 6.0f;
            hLb[q]  = vtb[q] + vtb[q+1];
            hT4a[q] = vpTa[q] + vpTa[q+1] - 4.0f;
            hB4a[q] = vpBa[q] + vpBa[q+1] - 4.0f;
            hTb[q]  = vpTb[q] + vpTb[q+1];
            hBb[q]  = vpBb[q] + vpBb[q+1];
        }
        #pragma unroll
        for (int q = 0; q < 4; ++q) {
            hU6a[q] = hT4a[q] + vpTa[q+2] - 2.0f;   // (pair-4) + third - 2 == triple - 6
            hD6a[q] = hB4a[q] + vpBa[q+2] - 2.0f;
            hUb[q]  = hTb[q] + vpTb[q+2];
            hDb[q]  = hBb[q] + vpBb[q+2];
        }

        const float* imrow = &sx[(oy + 2) * SXW + ox0 + 2];
        float2 i01 = *(const float2*)imrow;
        float2 i23 = *(const float2*)(imrow + 2);
        float imv[4] = { i01.x, i01.y, i23.x, i23.y };

        float res[4];
        #pragma unroll
        for (int vc = 0; vc < 4; ++vc) {
            float im = imv[vc];
            // g = (sumA - n)*im + sumB ; reference order L,R,U,D,NW,NE,SW,SE
            float g0 = fmaf(hL6a[vc],   im, hLb[vc]);     // L
            float g1 = fmaf(hL6a[vc+1], im, hLb[vc+1]);   // R
            float g2 = fmaf(hU6a[vc],   im, hUb[vc]);     // U
            float g3 = fmaf(hD6a[vc],   im, hDb[vc]);     // D
            float h0 = fmaf(hT4a[vc],   im, hTb[vc]);     // NW
            float h1 = fmaf(hT4a[vc+1], im, hTb[vc+1]);   // NE
            float h2 = fmaf(hB4a[vc],   im, hBb[vc]);     // SW
            float h3 = fmaf(hB4a[vc+1], im, hBb[vc+1]);   // SE

            float d6 = fabsf(g0), b6 = g0;
            if (fabsf(g1) < d6) { d6 = fabsf(g1); b6 = g1; }
            if (fabsf(g2) < d6) { d6 = fabsf(g2); b6 = g2; }
            if (fabsf(g3) < d6) { d6 = fabsf(g3); b6 = g3; }
            float d4 = fabsf(h0), b4 = h0;
            if (fabsf(h1) < d4) { d4 = fabsf(h1); b4 = h1; }
            if (fabsf(h2) < d4) { d4 = fabsf(h2); b4 = h2; }
            if (fabsf(h3) < d4) { d4 = fabsf(h3); b4 = h3; }

            // |g4|/4 < |g6|/6  <=>  3*d4 < 2*d6 (tie -> /6 group, reference order)
            float v6 = fmaf(b6, 1.0f / 6.0f, im);
            float v4 = fmaf(b4, 0.25f, im);
            float val = (3.0f * d4 < 2.0f * d6) ? v4 : v6;
            res[vc] = fminf(fmaxf(truncf(val), 0.0f), 255.0f);
        }

        float* prow = po + (size_t)(gy0 + oy) * W + (gx0 + ox0);
        if (ox0 + 4 <= maxx) {
            // gx0+ox0 is even -> float2 stores are 8B-aligned (16B alignment not guaranteed)
            *(float2*)prow       = make_float2(res[0], res[1]);
            *(float2*)(prow + 2) = make_float2(res[2], res[3]);
        } else {
            #pragma unroll
            for (int vc = 0; vc < 4; ++vc)
                if (ox0 + vc < maxx) prow[vc] = res[vc];
        }
    }
    #undef LOADROW
}

extern "C" void kernel_launch(void* const* d_in, const int* in_sizes, int n_in,
                              void* d_out, int out_size)
{
    const float* lrx = (const float*)d_in[0];
    const float* lry = (const float*)d_in[1];
    // d_in[2] (hr_x) is unused by the reference computation.
    float* out = (float*)d_out;

    const int H = 2048, W = 2048;
    dim3 block(256);
    dim3 grid((W + TW - 1) / TW, (H + TH - 1) / TH, 3);
    fgf_kernel<<<grid, block>>>(lrx, lry, out, H, W);
}

// round 10
// speedup vs baseline: 1.0846x; 1.0047x over previous
#include <cuda_runtime.h>
#include <cuda_bf16.h>
#include <math.h>

// Fused FastGuidedFilter, 62x30 tile.
//   Conflict-free separate A/b smem planes. Row-streamed stage 2.
//   Stage 3: cross-row horizontal-sum reuse (hT(row1)=hB(row0), hU(row1)=hD(row0))
//   + FMNMX-tree grouped argmin: d=min tree of |g|, payload by first-equality select.
//   g = (sumA - n)*im + sumB ; cross-group 3|g4| < 2|g6|.
//   out = clip(trunc(best), 0, 255).  hr_x unused by reference.

#define TW 62
#define TH 30
#define SXW 68   // input smem stride (34 rows x 66 cols used)
#define SAW 64   // A/b smem stride (32 rows x 64 cols, exact)

__device__ __forceinline__ void emit_row(
    const float hL6a[5], const float hLb[5],
    const float hT4a[5], const float hTb[5],
    const float hB4a[5], const float hBb[5],
    const float hU6a[4], const float hUb[4],
    const float hD6a[4], const float hDb[4],
    const float imv[4], float res[4])
{
    #pragma unroll
    for (int vc = 0; vc < 4; ++vc) {
        const float im = imv[vc];
        // g = (sumA - n)*im + sumB ; reference order L,R,U,D then NW,NE,SW,SE
        float g0 = fmaf(hL6a[vc],   im, hLb[vc]);     // L
        float g1 = fmaf(hL6a[vc+1], im, hLb[vc+1]);   // R
        float g2 = fmaf(hU6a[vc],   im, hUb[vc]);     // U
        float g3 = fmaf(hD6a[vc],   im, hDb[vc]);     // D
        float h0 = fmaf(hT4a[vc],   im, hTb[vc]);     // NW
        float h1 = fmaf(hT4a[vc+1], im, hTb[vc+1]);   // NE
        float h2 = fmaf(hB4a[vc],   im, hBb[vc]);     // SW
        float h3 = fmaf(hB4a[vc+1], im, hBb[vc+1]);   // SE

        float e0 = fabsf(g0), e1 = fabsf(g1), e2 = fabsf(g2), e3 = fabsf(g3);
        float d6 = fminf(fminf(e0, e1), fminf(e2, e3));
        float b6 = (e0 == d6) ? g0 : (e1 == d6) ? g1 : (e2 == d6) ? g2 : g3;

        float f0 = fabsf(h0), f1 = fabsf(h1), f2 = fabsf(h2), f3 = fabsf(h3);
        float d4 = fminf(fminf(f0, f1), fminf(f2, f3));
        float b4 = (f0 == d4) ? h0 : (f1 == d4) ? h1 : (f2 == d4) ? h2 : h3;

        // |g4|/4 < |g6|/6  <=>  3*d4 < 2*d6 (tie -> /6 group, reference order)
        float v6 = fmaf(b6, 1.0f / 6.0f, im);
        float v4 = fmaf(b4, 0.25f, im);
        float val = (3.0f * d4 < 2.0f * d6) ? v4 : v6;
        res[vc] = fminf(fmaxf(truncf(val), 0.0f), 255.0f);
    }
}

__global__ __launch_bounds__(256, 4)
void fgf_kernel(const float* __restrict__ lrx,
                const float* __restrict__ lry,
                float* __restrict__ out,
                int H, int W)
{
    __shared__ float sx[34 * SXW];
    __shared__ float sy[34 * SXW];
    __shared__ float sA[33 * SAW + 8];   // +8 pad for edge col overread
    __shared__ float sB[33 * SAW + 8];

    const int tid = threadIdx.x;
    const int c   = blockIdx.z;
    const int gx0 = blockIdx.x * TW;
    const int gy0 = blockIdx.y * TH;
    const float* __restrict__ px = lrx + (size_t)c * H * W;
    const float* __restrict__ py = lry + (size_t)c * H * W;

    const bool xin = (gx0 >= 2) && (gx0 + TW + 2 <= W);
    const bool yin = (gy0 >= 2) && (gy0 + TH + 2 <= H);
    const bool inner = xin && yin;

    // ---- stage 1: load 34x66 halo tile (clamp == replicate pad) ----
    if (xin) {
        #pragma unroll
        for (int it = 0; it < 5; ++it) {
            int i = tid + it * 256;
            if (i < 1122) {                       // 33 float2 per row x 34 rows
                int r = i / 33;
                int q = (i - r * 33) * 2;
                int gy = gy0 + r - 2; gy = max(0, min(H - 1, gy));
                const float2 vx = *(const float2*)(px + (size_t)gy * W + (gx0 - 2) + q);
                const float2 vy = *(const float2*)(py + (size_t)gy * W + (gx0 - 2) + q);
                *(float2*)&sx[r * SXW + q] = vx;
                *(float2*)&sy[r * SXW + q] = vy;
            }
        }
    } else {
        for (int i = tid; i < 34 * 66; i += 256) {
            int r = i / 66;
            int q = i - r * 66;
            int gy = gy0 + r - 2; gy = max(0, min(H - 1, gy));
            int gx = gx0 + q - 2; gx = max(0, min(W - 1, gx));
            size_t g = (size_t)gy * W + gx;
            sx[r * SXW + q] = px[g];
            sy[r * SXW + q] = py[g];
        }
    }
    __syncthreads();

    // ---- stage 2: A,b on exact 32x64 grid, one 2x4 chunk per thread, row-streamed ----
    {
        const int cr = tid >> 4;          // 0..15
        const int cq = tid & 15;          // 0..15
        const int r0 = cr * 2, q0 = cq * 4;

        float S0x[4], S0y[4], S0xy[4], S0xx[4];
        float S1x[4], S1y[4], S1xy[4], S1xx[4];

        #pragma unroll
        for (int u = 0; u < 4; ++u) {
            const float* bx = &sx[(r0 + u) * SXW + q0];
            const float* by = &sy[(r0 + u) * SXW + q0];
            float4 x4 = *(const float4*)bx;
            float2 x2 = *(const float2*)(bx + 4);
            float4 y4 = *(const float4*)by;
            float2 y2 = *(const float2*)(by + 4);
            float xr[6] = { x4.x, x4.y, x4.z, x4.w, x2.x, x2.y };
            float yr[6] = { y4.x, y4.y, y4.z, y4.w, y2.x, y2.y };

            float hx[4], hy[4], hxy[4], hxx[4];
            #pragma unroll
            for (int d = 0; d < 4; ++d) {
                hx[d]  = xr[d] + xr[d+1] + xr[d+2];
                hy[d]  = yr[d] + yr[d+1] + yr[d+2];
                hxy[d] = fmaf(xr[d], yr[d], fmaf(xr[d+1], yr[d+1], xr[d+2] * yr[d+2]));
                hxx[d] = fmaf(xr[d], xr[d], fmaf(xr[d+1], xr[d+1], xr[d+2] * xr[d+2]));
            }
            if (u == 0) {
                #pragma unroll
                for (int d = 0; d < 4; ++d) { S0x[d] = hx[d]; S0y[d] = hy[d]; S0xy[d] = hxy[d]; S0xx[d] = hxx[d]; }
            } else if (u == 1) {
                #pragma unroll
                for (int d = 0; d < 4; ++d) {
                    S0x[d] += hx[d]; S0y[d] += hy[d]; S0xy[d] += hxy[d]; S0xx[d] += hxx[d];
                    S1x[d]  = hx[d]; S1y[d]  = hy[d]; S1xy[d]  = hxy[d]; S1xx[d]  = hxx[d];
                }
            } else if (u == 2) {
                #pragma unroll
                for (int d = 0; d < 4; ++d) {
                    S0x[d] += hx[d]; S0y[d] += hy[d]; S0xy[d] += hxy[d]; S0xx[d] += hxx[d];
                    S1x[d] += hx[d]; S1y[d] += hy[d]; S1xy[d] += hxy[d]; S1xx[d] += hxx[d];
                }
            } else {
                #pragma unroll
                for (int d = 0; d < 4; ++d) {
                    S1x[d] += hx[d]; S1y[d] += hy[d]; S1xy[d] += hxy[d]; S1xx[d] += hxx[d];
                }
            }
        }

        #pragma unroll
        for (int dr = 0; dr < 2; ++dr) {
            float Ao[4], Bo[4];
            #pragma unroll
            for (int dc = 0; dc < 4; ++dc) {
                float sxv = dr ? S1x[dc]  : S0x[dc];
                float syv = dr ? S1y[dc]  : S0y[dc];
                float sxy = dr ? S1xy[dc] : S0xy[dc];
                float sxx = dr ? S1xx[dc] : S0xx[dc];
                float t   = sxv * (-1.0f / 9.0f);
                float num = fmaf(t, syv, sxy);
                float den = fmaf(t, sxv, sxx) + 9e-4f;
                float A = __fdividef(num, den);
                float B = (syv - A * sxv) * (1.0f / 9.0f);
                if (!inner) {
                    int gy = gy0 + r0 + dr - 1;
                    int gx = gx0 + q0 + dc - 1;
                    if (gy < 0 || gy >= H || gx < 0 || gx >= W) { A = 0.0f; B = 0.0f; }
                }
                Ao[dc] = A; Bo[dc] = B;
            }
            *(float4*)&sA[(r0 + dr) * SAW + q0] = make_float4(Ao[0], Ao[1], Ao[2], Ao[3]);
            *(float4*)&sB[(r0 + dr) * SAW + q0] = make_float4(Bo[0], Bo[1], Bo[2], Bo[3]);
        }
    }
    __syncthreads();

    // ---- stage 3: 2 rows x 4 cols per thread with cross-row h-sum reuse ----
    const int maxy = min(TH, H - gy0);
    const int maxx = min(TW, W - gx0);
    const int ty  = tid >> 4;        // 0..15
    const int tx  = tid & 15;        // 0..15
    const int oy0 = ty * 2, ox0 = tx * 4;

    if (oy0 >= maxy || ox0 >= maxx) return;   // no syncs after this point

    float* __restrict__ po = out + (size_t)c * H * W;

    #define LOADROW(arr, plane, row) { \
        const float* p_ = &plane[(row) * SAW + ox0]; \
        float4 v4_ = *(const float4*)p_; \
        float2 v2_ = *(const float2*)(p_ + 4); \
        arr[0] = v4_.x; arr[1] = v4_.y; arr[2] = v4_.z; arr[3] = v4_.w; arr[4] = v2_.x; arr[5] = v2_.y; }

    #define STOREROW(oy, res) { \
        float* prow = po + (size_t)(gy0 + (oy)) * W + (gx0 + ox0); \
        if (ox0 + 4 <= maxx) { \
            *(float2*)prow       = make_float2(res[0], res[1]); \
            *(float2*)(prow + 2) = make_float2(res[2], res[3]); \
        } else { \
            _Pragma("unroll") \
            for (int vc = 0; vc < 4; ++vc) \
                if (ox0 + vc < maxx) prow[vc] = res[vc]; \
        } }

    // ---- row 0 ----
    float vpBa[6], vpBb[6];                 // bottom vertical pairs (live into row1)
    float hB4a[5], hBb[5], hD6a[4], hDb[4]; // bottom h-sums (renamed into row1's top)
    {
        float a0[6], b0[6], a1[6], b1[6], a2r[6], b2r[6];
        LOADROW(a0, sA, oy0);     LOADROW(b0, sB, oy0);
        LOADROW(a1, sA, oy0 + 1); LOADROW(b1, sB, oy0 + 1);
        LOADROW(a2r, sA, oy0 + 2); LOADROW(b2r, sB, oy0 + 2);

        float vpTa[6], vta[6], vpTb[6], vtb[6];
        #pragma unroll
        for (int v = 0; v < 6; ++v) {
            vpTa[v] = a0[v] + a1[v];
            vpBa[v] = a1[v] + a2r[v];
            vta[v]  = vpTa[v] + a2r[v];
            vpTb[v] = b0[v] + b1[v];
            vpBb[v] = b1[v] + b2r[v];
            vtb[v]  = vpTb[v] + b2r[v];
        }

        float hL6a[5], hLb[5], hT4a[5], hTb[5];
        float hU6a[4], hUb[4];
        #pragma unroll
        for (int q = 0; q < 5; ++q) {
            hL6a[q] = vta[q] + vta[q+1] - 6.0f;
            hLb[q]  = vtb[q] + vtb[q+1];
            hT4a[q] = vpTa[q] + vpTa[q+1] - 4.0f;
            hTb[q]  = vpTb[q] + vpTb[q+1];
            hB4a[q] = vpBa[q] + vpBa[q+1] - 4.0f;
            hBb[q]  = vpBb[q] + vpBb[q+1];
        }
        #pragma unroll
        for (int q = 0; q < 4; ++q) {
            hU6a[q] = hT4a[q] + vpTa[q+2] - 2.0f;
            hUb[q]  = hTb[q] + vpTb[q+2];
            hD6a[q] = hB4a[q] + vpBa[q+2] - 2.0f;
            hDb[q]  = hBb[q] + vpBb[q+2];
        }

        const float* imrow = &sx[(oy0 + 2) * SXW + ox0 + 2];
        float2 i01 = *(const float2*)imrow;
        float2 i23 = *(const float2*)(imrow + 2);
        float imv[4] = { i01.x, i01.y, i23.x, i23.y };

        float res[4];
        emit_row(hL6a, hLb, hT4a, hTb, hB4a, hBb, hU6a, hUb, hD6a, hDb, imv, res);
        STOREROW(oy0, res);
    }

    // ---- row 1 (reuses: hT = row0's hB, hU = row0's hD) ----
    if (oy0 + 1 < maxy) {
        float a2r[6], b2r[6], a3[6], b3[6];
        LOADROW(a2r, sA, oy0 + 2); LOADROW(b2r, sB, oy0 + 2);
        LOADROW(a3,  sA, oy0 + 3); LOADROW(b3,  sB, oy0 + 3);

        float vpB1a[6], vt1a[6], vpB1b[6], vt1b[6];
        #pragma unroll
        for (int v = 0; v < 6; ++v) {
            vpB1a[v] = a2r[v] + a3[v];
            vt1a[v]  = vpBa[v] + a3[v];     // vpT(row1) == vpBa(row0)
            vpB1b[v] = b2r[v] + b3[v];
            vt1b[v]  = vpBb[v] + b3[v];
        }

        float hL1a[5], hL1b[5], hB1a[5], hB1b[5];
        float hD1a[4], hD1b[4];
        #pragma unroll
        for (int q = 0; q < 5; ++q) {
            hL1a[q] = vt1a[q] + vt1a[q+1] - 6.0f;
            hL1b[q] = vt1b[q] + vt1b[q+1];
            hB1a[q] = vpB1a[q] + vpB1a[q+1] - 4.0f;
            hB1b[q] = vpB1b[q] + vpB1b[q+1];
        }
        #pragma unroll
        for (int q = 0; q < 4; ++q) {
            hD1a[q] = hB1a[q] + vpB1a[q+2] - 2.0f;
            hD1b[q] = hB1b[q] + vpB1b[q+2];
        }

        const float* imrow = &sx[(oy0 + 3) * SXW + ox0 + 2];
        float2 i01 = *(const float2*)imrow;
        float2 i23 = *(const float2*)(imrow + 2);
        float imv[4] = { i01.x, i01.y, i23.x, i23.y };

        float res[4];
        // hT(row1)=hB4a(row0), hU(row1)=hD6a(row0)
        emit_row(hL1a, hL1b, hB4a, hBb, hB1a, hB1b, hD6a, hDb, hD1a, hD1b, imv, res);
        STOREROW(oy0 + 1, res);
    }
    #undef LOADROW
    #undef STOREROW
}

extern "C" void kernel_launch(void* const* d_in, const int* in_sizes, int n_in,
                              void* d_out, int out_size)
{
    const float* lrx = (const float*)d_in[0];
    const float* lry = (const float*)d_in[1];
    // d_in[2] (hr_x) is unused by the reference computation.
    float* out = (float*)d_out;

    const int H = 2048, W = 2048;
    dim3 block(256);
    dim3 grid((W + TW - 1) / TW, (H + TH - 1) / TH, 3);
    fgf_kernel<<<grid, block>>>(lrx, lry, out, H, W);
}

// round 11
// speedup vs baseline: 1.1204x; 1.0330x over previous
#include <cuda_runtime.h>
#include <cuda_bf16.h>
#include <math.h>

// Fused FastGuidedFilter, 62x30 tile.
//   Conflict-free separate A/b smem planes. Row-streamed stage 2.
//   Stage 1: division-free warp-structured halo load.
//   Stage 3: packed f32x2 vertical sums (natural float4 register pairs),
//            cross-row h-sum reuse, FMNMX-tree grouped argmin.
//   g = (sumA - n)*im + sumB ; cross-group 3|g4| < 2|g6|.
//   out = clip(trunc(best), 0, 255).  hr_x unused by reference.

#define TW 62
#define TH 30
#define SXW 68   // input smem stride (34 rows x 66 cols used)
#define SAW 64   // A/b smem stride (32 rows x 64 cols, exact)

typedef unsigned long long u64;
__device__ __forceinline__ u64 F2ADD(u64 a, u64 b) {
    u64 r; asm("add.rn.f32x2 %0, %1, %2;" : "=l"(r) : "l"(a), "l"(b)); return r;
}
__device__ __forceinline__ float F2LO(u64 v) {
    float a, b; asm("mov.b64 {%0, %1}, %2;" : "=f"(a), "=f"(b) : "l"(v)); return a;
}
__device__ __forceinline__ float F2HI(u64 v) {
    float a, b; asm("mov.b64 {%0, %1}, %2;" : "=f"(a), "=f"(b) : "l"(v)); return b;
}

__device__ __forceinline__ void emit_row(
    const float hL6a[5], const float hLb[5],
    const float hT4a[5], const float hTb[5],
    const float hB4a[5], const float hBb[5],
    const float hU6a[4], const float hUb[4],
    const float hD6a[4], const float hDb[4],
    const float imv[4], float res[4])
{
    #pragma unroll
    for (int vc = 0; vc < 4; ++vc) {
        const float im = imv[vc];
        // g = (sumA - n)*im + sumB ; reference order L,R,U,D then NW,NE,SW,SE
        float g0 = fmaf(hL6a[vc],   im, hLb[vc]);     // L
        float g1 = fmaf(hL6a[vc+1], im, hLb[vc+1]);   // R
        float g2 = fmaf(hU6a[vc],   im, hUb[vc]);     // U
        float g3 = fmaf(hD6a[vc],   im, hDb[vc]);     // D
        float h0 = fmaf(hT4a[vc],   im, hTb[vc]);     // NW
        float h1 = fmaf(hT4a[vc+1], im, hTb[vc+1]);   // NE
        float h2 = fmaf(hB4a[vc],   im, hBb[vc]);     // SW
        float h3 = fmaf(hB4a[vc+1], im, hBb[vc+1]);   // SE

        float e0 = fabsf(g0), e1 = fabsf(g1), e2 = fabsf(g2), e3 = fabsf(g3);
        float d6 = fminf(fminf(e0, e1), fminf(e2, e3));
        float b6 = (e0 == d6) ? g0 : (e1 == d6) ? g1 : (e2 == d6) ? g2 : g3;

        float f0 = fabsf(h0), f1 = fabsf(h1), f2 = fabsf(h2), f3 = fabsf(h3);
        float d4 = fminf(fminf(f0, f1), fminf(f2, f3));
        float b4 = (f0 == d4) ? h0 : (f1 == d4) ? h1 : (f2 == d4) ? h2 : h3;

        // |g4|/4 < |g6|/6  <=>  3*d4 < 2*d6 (tie -> /6 group, reference order)
        float v6 = fmaf(b6, 1.0f / 6.0f, im);
        float v4 = fmaf(b4, 0.25f, im);
        float val = (3.0f * d4 < 2.0f * d6) ? v4 : v6;
        res[vc] = fminf(fmaxf(truncf(val), 0.0f), 255.0f);
    }
}

__global__ __launch_bounds__(256, 4)
void fgf_kernel(const float* __restrict__ lrx,
                const float* __restrict__ lry,
                float* __restrict__ out,
                int H, int W)
{
    __shared__ float sx[34 * SXW];
    __shared__ float sy[34 * SXW];
    __shared__ float sA[33 * SAW + 8];   // +8 pad for edge col overread
    __shared__ float sB[33 * SAW + 8];

    const int tid = threadIdx.x;
    const int c   = blockIdx.z;
    const int gx0 = blockIdx.x * TW;
    const int gy0 = blockIdx.y * TH;
    const float* __restrict__ px = lrx + (size_t)c * H * W;
    const float* __restrict__ py = lry + (size_t)c * H * W;

    const bool xin = (gx0 >= 2) && (gx0 + TW + 2 <= W);
    const bool yin = (gy0 >= 2) && (gy0 + TH + 2 <= H);
    const bool inner = xin && yin;

    // ---- stage 1: load 34x66 halo tile (clamp == replicate pad) ----
    if (xin) {
        // division-free warp mapping: warp w -> rows {w, w+8, w+16, w+24, 32+w (w<2)}
        const int warp = tid >> 5;
        const int lane = tid & 31;
        const int q    = lane * 2;
        #pragma unroll
        for (int it = 0; it < 4; ++it) {
            int r  = warp + it * 8;
            int gy = gy0 + r - 2; gy = max(0, min(H - 1, gy));
            const float* rowx = px + (size_t)gy * W + (gx0 - 2);
            const float* rowy = py + (size_t)gy * W + (gx0 - 2);
            *(float2*)&sx[r * SXW + q] = *(const float2*)(rowx + q);
            *(float2*)&sy[r * SXW + q] = *(const float2*)(rowy + q);
            if (lane == 31) {   // 33rd pair (cols 64,65)
                *(float2*)&sx[r * SXW + 64] = *(const float2*)(rowx + 64);
                *(float2*)&sy[r * SXW + 64] = *(const float2*)(rowy + 64);
            }
        }
        if (warp < 2) {
            int r  = 32 + warp;
            int gy = gy0 + r - 2; gy = max(0, min(H - 1, gy));
            const float* rowx = px + (size_t)gy * W + (gx0 - 2);
            const float* rowy = py + (size_t)gy * W + (gx0 - 2);
            *(float2*)&sx[r * SXW + q] = *(const float2*)(rowx + q);
            *(float2*)&sy[r * SXW + q] = *(const float2*)(rowy + q);
            if (lane == 31) {
                *(float2*)&sx[r * SXW + 64] = *(const float2*)(rowx + 64);
                *(float2*)&sy[r * SXW + 64] = *(const float2*)(rowy + 64);
            }
        }
    } else {
        for (int i = tid; i < 34 * 66; i += 256) {
            int r = i / 66;
            int q = i - r * 66;
            int gy = gy0 + r - 2; gy = max(0, min(H - 1, gy));
            int gx = gx0 + q - 2; gx = max(0, min(W - 1, gx));
            size_t g = (size_t)gy * W + gx;
            sx[r * SXW + q] = px[g];
            sy[r * SXW + q] = py[g];
        }
    }
    __syncthreads();

    // ---- stage 2: A,b on exact 32x64 grid, one 2x4 chunk per thread, row-streamed ----
    {
        const int cr = tid >> 4;          // 0..15
        const int cq = tid & 15;          // 0..15
        const int r0 = cr * 2, q0 = cq * 4;

        float S0x[4], S0y[4], S0xy[4], S0xx[4];
        float S1x[4], S1y[4], S1xy[4], S1xx[4];

        #pragma unroll
        for (int u = 0; u < 4; ++u) {
            const float* bx = &sx[(r0 + u) * SXW + q0];
            const float* by = &sy[(r0 + u) * SXW + q0];
            float4 x4 = *(const float4*)bx;
            float2 x2 = *(const float2*)(bx + 4);
            float4 y4 = *(const float4*)by;
            float2 y2 = *(const float2*)(by + 4);
            float xr[6] = { x4.x, x4.y, x4.z, x4.w, x2.x, x2.y };
            float yr[6] = { y4.x, y4.y, y4.z, y4.w, y2.x, y2.y };

            float hx[4], hy[4], hxy[4], hxx[4];
            #pragma unroll
            for (int d = 0; d < 4; ++d) {
                hx[d]  = xr[d] + xr[d+1] + xr[d+2];
                hy[d]  = yr[d] + yr[d+1] + yr[d+2];
                hxy[d] = fmaf(xr[d], yr[d], fmaf(xr[d+1], yr[d+1], xr[d+2] * yr[d+2]));
                hxx[d] = fmaf(xr[d], xr[d], fmaf(xr[d+1], xr[d+1], xr[d+2] * xr[d+2]));
            }
            if (u == 0) {
                #pragma unroll
                for (int d = 0; d < 4; ++d) { S0x[d] = hx[d]; S0y[d] = hy[d]; S0xy[d] = hxy[d]; S0xx[d] = hxx[d]; }
            } else if (u == 1) {
                #pragma unroll
                for (int d = 0; d < 4; ++d) {
                    S0x[d] += hx[d]; S0y[d] += hy[d]; S0xy[d] += hxy[d]; S0xx[d] += hxx[d];
                    S1x[d]  = hx[d]; S1y[d]  = hy[d]; S1xy[d]  = hxy[d]; S1xx[d]  = hxx[d];
                }
            } else if (u == 2) {
                #pragma unroll
                for (int d = 0; d < 4; ++d) {
                    S0x[d] += hx[d]; S0y[d] += hy[d]; S0xy[d] += hxy[d]; S0xx[d] += hxx[d];
                    S1x[d] += hx[d]; S1y[d] += hy[d]; S1xy[d] += hxy[d]; S1xx[d] += hxx[d];
                }
            } else {
                #pragma unroll
                for (int d = 0; d < 4; ++d) {
                    S1x[d] += hx[d]; S1y[d] += hy[d]; S1xy[d] += hxy[d]; S1xx[d] += hxx[d];
                }
            }
        }

        #pragma unroll
        for (int dr = 0; dr < 2; ++dr) {
            float Ao[4], Bo[4];
            #pragma unroll
            for (int dc = 0; dc < 4; ++dc) {
                float sxv = dr ? S1x[dc]  : S0x[dc];
                float syv = dr ? S1y[dc]  : S0y[dc];
                float sxy = dr ? S1xy[dc] : S0xy[dc];
                float sxx = dr ? S1xx[dc] : S0xx[dc];
                float t   = sxv * (-1.0f / 9.0f);
                float num = fmaf(t, syv, sxy);
                float den = fmaf(t, sxv, sxx) + 9e-4f;
                float A = __fdividef(num, den);
                float B = (syv - A * sxv) * (1.0f / 9.0f);
                if (!inner) {
                    int gy = gy0 + r0 + dr - 1;
                    int gx = gx0 + q0 + dc - 1;
                    if (gy < 0 || gy >= H || gx < 0 || gx >= W) { A = 0.0f; B = 0.0f; }
                }
                Ao[dc] = A; Bo[dc] = B;
            }
            *(float4*)&sA[(r0 + dr) * SAW + q0] = make_float4(Ao[0], Ao[1], Ao[2], Ao[3]);
            *(float4*)&sB[(r0 + dr) * SAW + q0] = make_float4(Bo[0], Bo[1], Bo[2], Bo[3]);
        }
    }
    __syncthreads();

    // ---- stage 3: packed vertical sums + cross-row reuse + grouped argmin ----
    const int maxy = min(TH, H - gy0);
    const int maxx = min(TW, W - gx0);
    const int ty  = tid >> 4;        // 0..15
    const int tx  = tid & 15;        // 0..15
    const int oy0 = ty * 2, ox0 = tx * 4;

    if (oy0 >= maxy || ox0 >= maxx) return;   // no syncs after this point

    float* __restrict__ po = out + (size_t)c * H * W;

    // load one 6-col row as 3 f32x2 packs (16B-aligned: SAW=64, ox0 % 4 == 0)
    #define LOADROWP(P, plane, row) { \
        const float* p_ = &plane[(row) * SAW + ox0]; \
        ulonglong2 l2_ = *(const ulonglong2*)p_; \
        P[0] = l2_.x; P[1] = l2_.y; P[2] = *(const u64*)(p_ + 4); }

    #define STOREROW(oy, res) { \
        float* prow = po + (size_t)(gy0 + (oy)) * W + (gx0 + ox0); \
        if (ox0 + 4 <= maxx) { \
            *(float2*)prow       = make_float2(res[0], res[1]); \
            *(float2*)(prow + 2) = make_float2(res[2], res[3]); \
        } else { \
            _Pragma("unroll") \
            for (int vc = 0; vc < 4; ++vc) \
                if (ox0 + vc < maxx) prow[vc] = res[vc]; \
        } }

    #define UNPACK6(arr, P) { \
        arr[0] = F2LO(P[0]); arr[1] = F2HI(P[0]); \
        arr[2] = F2LO(P[1]); arr[3] = F2HI(P[1]); \
        arr[4] = F2LO(P[2]); arr[5] = F2HI(P[2]); }

    u64 vpBaP[3], vpBbP[3];                 // bottom vertical pairs (live into row1)
    float hB4a[5], hBb[5], hD6a[4], hDb[4]; // bottom h-sums (renamed into row1's top)
    {
        u64 PA0[3], PA1[3], PA2[3], PB0[3], PB1[3], PB2[3];
        LOADROWP(PA0, sA, oy0);     LOADROWP(PB0, sB, oy0);
        LOADROWP(PA1, sA, oy0 + 1); LOADROWP(PB1, sB, oy0 + 1);
        LOADROWP(PA2, sA, oy0 + 2); LOADROWP(PB2, sB, oy0 + 2);

        u64 vpTaP[3], vtaP[3], vpTbP[3], vtbP[3];
        #pragma unroll
        for (int k = 0; k < 3; ++k) {
            vpTaP[k] = F2ADD(PA0[k], PA1[k]);
            vpBaP[k] = F2ADD(PA1[k], PA2[k]);
            vtaP[k]  = F2ADD(vpTaP[k], PA2[k]);
            vpTbP[k] = F2ADD(PB0[k], PB1[k]);
            vpBbP[k] = F2ADD(PB1[k], PB2[k]);
            vtbP[k]  = F2ADD(vpTbP[k], PB2[k]);
        }
        float vpTa[6], vpBa[6], vta[6], vpTb[6], vpBb[6], vtb[6];
        UNPACK6(vpTa, vpTaP); UNPACK6(vpBa, vpBaP); UNPACK6(vta, vtaP);
        UNPACK6(vpTb, vpTbP); UNPACK6(vpBb, vpBbP); UNPACK6(vtb, vtbP);

        float hL6a[5], hLb[5], hT4a[5], hTb[5];
        float hU6a[4], hUb[4];
        #pragma unroll
        for (int q = 0; q < 5; ++q) {
            hL6a[q] = vta[q] + vta[q+1] - 6.0f;
            hLb[q]  = vtb[q] + vtb[q+1];
            hT4a[q] = vpTa[q] + vpTa[q+1] - 4.0f;
            hTb[q]  = vpTb[q] + vpTb[q+1];
            hB4a[q] = vpBa[q] + vpBa[q+1] - 4.0f;
            hBb[q]  = vpBb[q] + vpBb[q+1];
        }
        #pragma unroll
        for (int q = 0; q < 4; ++q) {
            hU6a[q] = hT4a[q] + vpTa[q+2] - 2.0f;
            hUb[q]  = hTb[q] + vpTb[q+2];
            hD6a[q] = hB4a[q] + vpBa[q+2] - 2.0f;
            hDb[q]  = hBb[q] + vpBb[q+2];
        }

        const float* imrow = &sx[(oy0 + 2) * SXW + ox0 + 2];
        float2 i01 = *(const float2*)imrow;
        float2 i23 = *(const float2*)(imrow + 2);
        float imv[4] = { i01.x, i01.y, i23.x, i23.y };

        float res[4];
        emit_row(hL6a, hLb, hT4a, hTb, hB4a, hBb, hU6a, hUb, hD6a, hDb, imv, res);
        STOREROW(oy0, res);
    }

    // ---- row 1 (reuses: hT = row0's hB, hU = row0's hD; vpT = row0's vpB) ----
    if (oy0 + 1 < maxy) {
        u64 PA2[3], PB2[3], PA3[3], PB3[3];
        LOADROWP(PA2, sA, oy0 + 2); LOADROWP(PB2, sB, oy0 + 2);
        LOADROWP(PA3, sA, oy0 + 3); LOADROWP(PB3, sB, oy0 + 3);

        u64 vpB1aP[3], vt1aP[3], vpB1bP[3], vt1bP[3];
        #pragma unroll
        for (int k = 0; k < 3; ++k) {
            vpB1aP[k] = F2ADD(PA2[k], PA3[k]);
            vt1aP[k]  = F2ADD(vpBaP[k], PA3[k]);   // vpT(row1) == vpB(row0)
            vpB1bP[k] = F2ADD(PB2[k], PB3[k]);
            vt1bP[k]  = F2ADD(vpBbP[k], PB3[k]);
        }
        float vpB1a[6], vt1a[6], vpB1b[6], vt1b[6];
        UNPACK6(vpB1a, vpB1aP); UNPACK6(vt1a, vt1aP);
        UNPACK6(vpB1b, vpB1bP); UNPACK6(vt1b, vt1bP);

        float hL1a[5], hL1b[5], hB1a[5], hB1b[5];
        float hD1a[4], hD1b[4];
        #pragma unroll
        for (int q = 0; q < 5; ++q) {
            hL1a[q] = vt1a[q] + vt1a[q+1] - 6.0f;
            hL1b[q] = vt1b[q] + vt1b[q+1];
            hB1a[q] = vpB1a[q] + vpB1a[q+1] - 4.0f;
            hB1b[q] = vpB1b[q] + vpB1b[q+1];
        }
        #pragma unroll
        for (int q = 0; q < 4; ++q) {
            hD1a[q] = hB1a[q] + vpB1a[q+2] - 2.0f;
            hD1b[q] = hB1b[q] + vpB1b[q+2];
        }

        const float* imrow = &sx[(oy0 + 3) * SXW + ox0 + 2];
        float2 i01 = *(const float2*)imrow;
        float2 i23 = *(const float2*)(imrow + 2);
        float imv[4] = { i01.x, i01.y, i23.x, i23.y };

        float res[4];
        // hT(row1)=hB4a(row0), hU(row1)=hD6a(row0)
        emit_row(hL1a, hL1b, hB4a, hBb, hB1a, hB1b, hD6a, hDb, hD1a, hD1b, imv, res);
        STOREROW(oy0 + 1, res);
    }
    #undef LOADROWP
    #undef STOREROW
    #undef UNPACK6
}

extern "C" void kernel_launch(void* const* d_in, const int* in_sizes, int n_in,
                              void* d_out, int out_size)
{
    const float* lrx = (const float*)d_in[0];
    const float* lry = (const float*)d_in[1];
    // d_in[2] (hr_x) is unused by the reference computation.
    float* out = (float*)d_out;

    const int H = 2048, W = 2048;
    dim3 block(256);
    dim3 grid((W + TW - 1) / TW, (H + TH - 1) / TH, 3);
    fgf_kernel<<<grid, block>>>(lrx, lry, out, H, W);
}

// round 12
// speedup vs baseline: 1.1423x; 1.0196x over previous
#include <cuda_runtime.h>
#include <cuda_bf16.h>
#include <math.h>

// Fused FastGuidedFilter, 62x30 tile, packed f32x2 with even/odd split planes.
//   Input planes sxyE/sxyO hold (x,y) pairs for even/odd columns (conflict-free:
//   16B lane spacing). A/b planes sabE/sabO hold (A,b) pairs likewise.
//   stage 2: packed (sx,sy)/(sxx,sxy) box-stat chains -> A,b
//   stage 3: packed (A,b) vertical+horizontal sums, shift consts folded,
//            cross-row reuse, FMNMX-tree grouped argmin.
//   g = (sumA - n)*im + sumB ; cross-group 3|g4| < 2|g6|.
//   out = clip(trunc(best), 0, 255).  hr_x unused by reference.

#define TW 62
#define TH 30
#define SEW 68    // E/O input plane stride in floats (33 pairs = 66 used)
#define SAEW 68   // E/O A-b plane stride in floats (32 pairs = 64 used)

typedef unsigned long long u64;
__device__ __forceinline__ u64 F2ADD(u64 a, u64 b) {
    u64 r; asm("add.rn.f32x2 %0, %1, %2;" : "=l"(r) : "l"(a), "l"(b)); return r;
}
__device__ __forceinline__ u64 F2MUL(u64 a, u64 b) {
    u64 r; asm("mul.rn.f32x2 %0, %1, %2;" : "=l"(r) : "l"(a), "l"(b)); return r;
}
__device__ __forceinline__ u64 F2PK(float a, float b) {
    u64 r; asm("mov.b64 %0, {%1, %2};" : "=l"(r) : "f"(a), "f"(b)); return r;
}
__device__ __forceinline__ void F2UP(u64 v, float& a, float& b) {
    asm("mov.b64 {%0, %1}, %2;" : "=f"(a), "=f"(b) : "l"(v));
}
__device__ __forceinline__ u64 F2DUPLO(u64 v) {
    u64 r;
    asm("{ .reg .f32 lo, hi;\n\t"
        "  mov.b64 {lo, hi}, %1;\n\t"
        "  mov.b64 %0, {lo, lo}; }"
        : "=l"(r) : "l"(v));
    return r;
}

__device__ __forceinline__ void emit_row(
    const u64 hL[5], const u64 hT[5], const u64 hB[5],
    const u64 hU[4], const u64 hD[4],
    const float imv[4], float res[4])
{
    #pragma unroll
    for (int vc = 0; vc < 4; ++vc) {
        const float im = imv[vc];
        float a, b;
        // g = (sumA - n)*im + sumB ; reference order L,R,U,D then NW,NE,SW,SE
        F2UP(hL[vc],   a, b); float g0 = fmaf(a, im, b);   // L
        F2UP(hL[vc+1], a, b); float g1 = fmaf(a, im, b);   // R
        F2UP(hU[vc],   a, b); float g2 = fmaf(a, im, b);   // U
        F2UP(hD[vc],   a, b); float g3 = fmaf(a, im, b);   // D
        F2UP(hT[vc],   a, b); float h0 = fmaf(a, im, b);   // NW
        F2UP(hT[vc+1], a, b); float h1 = fmaf(a, im, b);   // NE
        F2UP(hB[vc],   a, b); float h2 = fmaf(a, im, b);   // SW
        F2UP(hB[vc+1], a, b); float h3 = fmaf(a, im, b);   // SE

        float e0 = fabsf(g0), e1 = fabsf(g1), e2 = fabsf(g2), e3 = fabsf(g3);
        float d6 = fminf(fminf(e0, e1), fminf(e2, e3));
        float b6 = (e0 == d6) ? g0 : (e1 == d6) ? g1 : (e2 == d6) ? g2 : g3;

        float f0 = fabsf(h0), f1 = fabsf(h1), f2 = fabsf(h2), f3 = fabsf(h3);
        float d4 = fminf(fminf(f0, f1), fminf(f2, f3));
        float b4 = (f0 == d4) ? h0 : (f1 == d4) ? h1 : (f2 == d4) ? h2 : h3;

        // |g4|/4 < |g6|/6  <=>  3*d4 < 2*d6 (tie -> /6 group, reference order)
        float v6 = fmaf(b6, 1.0f / 6.0f, im);
        float v4 = fmaf(b4, 0.25f, im);
        float val = (3.0f * d4 < 2.0f * d6) ? v4 : v6;
        res[vc] = fminf(fmaxf(truncf(val), 0.0f), 255.0f);
    }
}

__global__ __launch_bounds__(256, 4)
void fgf_kernel(const float* __restrict__ lrx,
                const float* __restrict__ lry,
                float* __restrict__ out,
                int H, int W)
{
    __shared__ __align__(16) float sxyE[34 * SEW];   // (x,y) pairs, even cols
    __shared__ __align__(16) float sxyO[34 * SEW];   // (x,y) pairs, odd cols
    __shared__ __align__(16) float sabE[32 * SAEW];  // (A,b) pairs, even cols
    __shared__ __align__(16) float sabO[32 * SAEW];  // (A,b) pairs, odd cols

    const int tid = threadIdx.x;
    const int c   = blockIdx.z;
    const int gx0 = blockIdx.x * TW;
    const int gy0 = blockIdx.y * TH;
    const float* __restrict__ px = lrx + (size_t)c * H * W;
    const float* __restrict__ py = lry + (size_t)c * H * W;

    const bool xin = (gx0 >= 2) && (gx0 + TW + 2 <= W);
    const bool yin = (gy0 >= 2) && (gy0 + TH + 2 <= H);
    const bool inner = xin && yin;

    // ---- stage 1: load 34x66 halo tile into (x,y) even/odd planes ----
    if (xin) {
        const int warp = tid >> 5;
        const int lane = tid & 31;
        #pragma unroll
        for (int it = 0; it < 4; ++it) {
            int r  = warp + it * 8;
            int gy = gy0 + r - 2; gy = max(0, min(H - 1, gy));
            const float* rowx = px + (size_t)gy * W + (gx0 - 2);
            const float* rowy = py + (size_t)gy * W + (gx0 - 2);
            float2 vx = *(const float2*)(rowx + lane * 2);
            float2 vy = *(const float2*)(rowy + lane * 2);
            *(float2*)&sxyE[r * SEW + lane * 2] = make_float2(vx.x, vy.x);
            *(float2*)&sxyO[r * SEW + lane * 2] = make_float2(vx.y, vy.y);
            if (lane == 31) {   // 33rd pair: cols 64,65
                float2 wx = *(const float2*)(rowx + 64);
                float2 wy = *(const float2*)(rowy + 64);
                *(float2*)&sxyE[r * SEW + 64] = make_float2(wx.x, wy.x);
                *(float2*)&sxyO[r * SEW + 64] = make_float2(wx.y, wy.y);
            }
        }
        if (warp < 2) {
            int r  = 32 + warp;
            int gy = gy0 + r - 2; gy = max(0, min(H - 1, gy));
            const float* rowx = px + (size_t)gy * W + (gx0 - 2);
            const float* rowy = py + (size_t)gy * W + (gx0 - 2);
            float2 vx = *(const float2*)(rowx + lane * 2);
            float2 vy = *(const float2*)(rowy + lane * 2);
            *(float2*)&sxyE[r * SEW + lane * 2] = make_float2(vx.x, vy.x);
            *(float2*)&sxyO[r * SEW + lane * 2] = make_float2(vx.y, vy.y);
            if (lane == 31) {
                float2 wx = *(const float2*)(rowx + 64);
                float2 wy = *(const float2*)(rowy + 64);
                *(float2*)&sxyE[r * SEW + 64] = make_float2(wx.x, wy.x);
                *(float2*)&sxyO[r * SEW + 64] = make_float2(wx.y, wy.y);
            }
        }
    } else {
        for (int i = tid; i < 34 * 66; i += 256) {
            int r = i / 66;
            int q = i - r * 66;
            int gy = gy0 + r - 2; gy = max(0, min(H - 1, gy));
            int gx = gx0 + q - 2; gx = max(0, min(W - 1, gx));
            size_t g = (size_t)gy * W + gx;
            float* plane = (q & 1) ? sxyO : sxyE;
            int off = r * SEW + (q & ~1);
            plane[off]     = px[g];
            plane[off + 1] = py[g];
        }
    }
    __syncthreads();

    // ---- stage 2: A,b on exact 32x64 grid, one 2x4 chunk per thread, packed stats ----
    {
        const int cr = tid >> 4;          // 0..15
        const int cq = tid & 15;          // 0..15
        const int r0 = cr * 2, q0 = cq * 4;
        const int fo = cq * 4;            // float offset in E/O planes

        u64 S0p[4], S0m[4], S1p[4], S1m[4];   // p=(sx,sy), m=(sxx,sxy)

        #pragma unroll
        for (int u = 0; u < 4; ++u) {
            const float* eb = &sxyE[(r0 + u) * SEW + fo];
            const float* ob = &sxyO[(r0 + u) * SEW + fo];
            ulonglong2 eL = *(const ulonglong2*)eb;
            u64 e2 = *(const u64*)(eb + 4);
            ulonglong2 oL = *(const ulonglong2*)ob;
            u64 o2 = *(const u64*)(ob + 4);
            u64 p[6] = { eL.x, oL.x, eL.y, oL.y, e2, o2 };   // cols q0..q0+5

            u64 m[6];
            #pragma unroll
            for (int v = 0; v < 6; ++v)
                m[v] = F2MUL(F2DUPLO(p[v]), p[v]);           // (x*x, x*y)

            u64 hp[4], hm[4];
            #pragma unroll
            for (int d = 0; d < 4; ++d) {
                hp[d] = F2ADD(F2ADD(p[d], p[d + 1]), p[d + 2]);
                hm[d] = F2ADD(F2ADD(m[d], m[d + 1]), m[d + 2]);
            }

            if (u == 0) {
                #pragma unroll
                for (int d = 0; d < 4; ++d) { S0p[d] = hp[d]; S0m[d] = hm[d]; }
            } else if (u == 1) {
                #pragma unroll
                for (int d = 0; d < 4; ++d) {
                    S0p[d] = F2ADD(S0p[d], hp[d]); S0m[d] = F2ADD(S0m[d], hm[d]);
                    S1p[d] = hp[d];                S1m[d] = hm[d];
                }
            } else if (u == 2) {
                #pragma unroll
                for (int d = 0; d < 4; ++d) {
                    S0p[d] = F2ADD(S0p[d], hp[d]); S0m[d] = F2ADD(S0m[d], hm[d]);
                    S1p[d] = F2ADD(S1p[d], hp[d]); S1m[d] = F2ADD(S1m[d], hm[d]);
                }
            } else {
                #pragma unroll
                for (int d = 0; d < 4; ++d) {
                    S1p[d] = F2ADD(S1p[d], hp[d]); S1m[d] = F2ADD(S1m[d], hm[d]);
                }
            }
        }

        #pragma unroll
        for (int dr = 0; dr < 2; ++dr) {
            float Ao[4], Bo[4];
            #pragma unroll
            for (int dc = 0; dc < 4; ++dc) {
                float sxv, syv, sxx, sxy_;
                F2UP(dr ? S1p[dc] : S0p[dc], sxv, syv);
                F2UP(dr ? S1m[dc] : S0m[dc], sxx, sxy_);
                // A = (sxy - sx*sy/9)/(sxx - sx*sx/9 + 9*eps); b = (sy - A*sx)/9
                float t   = sxv * (-1.0f / 9.0f);
                float num = fmaf(t, syv, sxy_);
                float den = fmaf(t, sxv, sxx) + 9e-4f;
                float A = __fdividef(num, den);
                float B = (syv - A * sxv) * (1.0f / 9.0f);
                if (!inner) {
                    int gy = gy0 + r0 + dr - 1;
                    int gx = gx0 + q0 + dc - 1;
                    if (gy < 0 || gy >= H || gx < 0 || gx >= W) { A = 0.0f; B = 0.0f; }
                }
                Ao[dc] = A; Bo[dc] = B;
            }
            *(float4*)&sabE[(r0 + dr) * SAEW + fo] = make_float4(Ao[0], Bo[0], Ao[2], Bo[2]);
            *(float4*)&sabO[(r0 + dr) * SAEW + fo] = make_float4(Ao[1], Bo[1], Ao[3], Bo[3]);
        }
    }
    __syncthreads();

    // ---- stage 3: packed (A,b) sums + cross-row reuse + grouped argmin ----
    const int maxy = min(TH, H - gy0);
    const int maxx = min(TW, W - gx0);
    const int ty  = tid >> 4;        // 0..15
    const int tx  = tid & 15;        // 0..15
    const int oy0 = ty * 2, ox0 = tx * 4;
    const int fo  = tx * 4;          // float offset in E/O planes

    if (oy0 >= maxy || ox0 >= maxx) return;   // no syncs after this point

    float* __restrict__ po = out + (size_t)c * H * W;

    // load one row of 6 (A,b) column-pairs from E/O planes (conflict-free)
    #define LOADAB(C, row) { \
        const float* e_ = &sabE[(row) * SAEW + fo]; \
        const float* o_ = &sabO[(row) * SAEW + fo]; \
        ulonglong2 eL_ = *(const ulonglong2*)e_; \
        ulonglong2 oL_ = *(const ulonglong2*)o_; \
        C[0] = eL_.x; C[1] = oL_.x; C[2] = eL_.y; C[3] = oL_.y; \
        C[4] = *(const u64*)(e_ + 4); C[5] = *(const u64*)(o_ + 4); }

    #define STOREROW(oy, res) { \
        float* prow = po + (size_t)(gy0 + (oy)) * W + (gx0 + ox0); \
        if (ox0 + 4 <= maxx) { \
            *(float2*)prow       = make_float2(res[0], res[1]); \
            *(float2*)(prow + 2) = make_float2(res[2], res[3]); \
        } else { \
            _Pragma("unroll") \
            for (int vc = 0; vc < 4; ++vc) \
                if (ox0 + vc < maxx) prow[vc] = res[vc]; \
        } }

    // im values for output row oy: x components at cols ox0+2..ox0+5
    #define LOADIM(imv, oy) { \
        const float* e_ = &sxyE[((oy) + 2) * SEW + fo + 2]; \
        const float* o_ = &sxyO[((oy) + 2) * SEW + fo + 2]; \
        imv[0] = ((const float2*)e_)->x; \
        imv[1] = ((const float2*)o_)->x; \
        imv[2] = ((const float2*)(e_ + 2))->x; \
        imv[3] = ((const float2*)(o_ + 2))->x; }

    const u64 C6 = F2PK(-6.0f, 0.0f);
    const u64 C4 = F2PK(-4.0f, 0.0f);
    const u64 C2 = F2PK(-2.0f, 0.0f);

    u64 vpB[6];                    // bottom vertical pairs (live into row1)
    u64 hB[5], hD[4];              // bottom h-sums (renamed into row1's top)
    {
        u64 R0[6], R1[6], R2[6];
        LOADAB(R0, oy0);
        LOADAB(R1, oy0 + 1);
        LOADAB(R2, oy0 + 2);

        u64 vpT[6], vt[6];
        #pragma unroll
        for (int v = 0; v < 6; ++v) {
            vpT[v] = F2ADD(R0[v], R1[v]);
            vpB[v] = F2ADD(R1[v], R2[v]);
            vt[v]  = F2ADD(vpT[v], R2[v]);
        }

        u64 hL[5], hT[5], hU[4], hDl[4];
        #pragma unroll
        for (int q = 0; q < 5; ++q) {
            hL[q] = F2ADD(F2ADD(vt[q],  vt[q + 1]),  C6);
            hT[q] = F2ADD(F2ADD(vpT[q], vpT[q + 1]), C4);
            hB[q] = F2ADD(F2ADD(vpB[q], vpB[q + 1]), C4);
        }
        #pragma unroll
        for (int q = 0; q < 4; ++q) {
            hU[q]  = F2ADD(F2ADD(hT[q], vpT[q + 2]), C2);
            hDl[q] = F2ADD(F2ADD(hB[q], vpB[q + 2]), C2);
        }
        #pragma unroll
        for (int q = 0; q < 4; ++q) hD[q] = hDl[q];

        float imv[4], res[4];
        LOADIM(imv, oy0);
        emit_row(hL, hT, hB, hU, hD, imv, res);
        STOREROW(oy0, res);
    }

    // ---- row 1 (reuses: hT = row0's hB, hU = row0's hD; vpT = row0's vpB) ----
    if (oy0 + 1 < maxy) {
        u64 R2[6], R3[6];
        LOADAB(R2, oy0 + 2);
        LOADAB(R3, oy0 + 3);

        u64 vpB1[6], vt1[6];
        #pragma unroll
        for (int v = 0; v < 6; ++v) {
            vpB1[v] = F2ADD(R2[v], R3[v]);
            vt1[v]  = F2ADD(vpB[v], R3[v]);   // vpT(row1) == vpB(row0)
        }

        u64 hL1[5], hB1[5], hD1[4];
        #pragma unroll
        for (int q = 0; q < 5; ++q) {
            hL1[q] = F2ADD(F2ADD(vt1[q],  vt1[q + 1]),  C6);
            hB1[q] = F2ADD(F2ADD(vpB1[q], vpB1[q + 1]), C4);
        }
        #pragma unroll
        for (int q = 0; q < 4; ++q)
            hD1[q] = F2ADD(F2ADD(hB1[q], vpB1[q + 2]), C2);

        float imv[4], res[4];
        LOADIM(imv, oy0 + 1);
        // hT(row1)=hB(row0), hU(row1)=hD(row0)
        emit_row(hL1, hB, hB1, hD, hD1, imv, res);
        STOREROW(oy0 + 1, res);
    }
    #undef LOADAB
    #undef STOREROW
    #undef LOADIM
}

extern "C" void kernel_launch(void* const* d_in, const int* in_sizes, int n_in,
                              void* d_out, int out_size)
{
    const float* lrx = (const float*)d_in[0];
    const float* lry = (const float*)d_in[1];
    // d_in[2] (hr_x) is unused by the reference computation.
    float* out = (float*)d_out;

    const int H = 2048, W = 2048;
    dim3 block(256);
    dim3 grid((W + TW - 1) / TW, (H + TH - 1) / TH, 3);
    fgf_kernel<<<grid, block>>>(lrx, lry, out, H, W);
}